// round 7
// baseline (speedup 1.0000x reference)
#include <cuda_runtime.h>
#include <math.h>

#define BB 4
#define NN 1024
#define KNNK 16
#define N3 3072
#define NCOL 12288
#define CATC 352
#define EPSF 1e-12f

// ---- static scratch ----
__device__ __align__(16) float g_cat[BB * CATC * 3 * NN];     // [b][c][d][n]
__device__ __align__(16) float g_Out[(size_t)NCOL * 512];     // [cid][og]
__device__ __align__(16) float g_Wall[512 * 128];             // [og][c]
__device__ __align__(16) float g_Dc[NCOL];
__device__ __align__(16) float g_ycc[BB * 128 * 3 * NN];
__device__ __align__(16) float g_y[BB * 128 * 3];
__device__ int g_idx[BB * NN * KNNK];

// ---- f32x2 helpers (Blackwell packed fp32) ----
__device__ __forceinline__ void fma2(unsigned long long& d,
                                     unsigned long long a, unsigned long long b) {
    asm("fma.rn.f32x2 %0, %1, %2, %0;" : "+l"(d) : "l"(a), "l"(b));
}
__device__ __forceinline__ unsigned long long packf2(float x, float y) {
    unsigned long long r;
    asm("mov.b64 %0, {%1, %2};" : "=l"(r) : "f"(x), "f"(y));
    return r;
}
__device__ __forceinline__ float2 unpackf2(unsigned long long v) {
    float2 r;
    asm("mov.b64 {%0, %1}, %2;" : "=f"(r.x), "=f"(r.y) : "l"(v));
    return r;
}

// ---- KNN (PROTECTED rounding structure — do not change) ----
__global__ void knn_k(const float* __restrict__ x) {
    __shared__ float ssq[NN];
    __shared__ float sd[NN];
    __shared__ float rv[8];
    __shared__ int   ri[8];
    int bn = blockIdx.x;
    int b = bn >> 10, n = bn & (NN - 1);
    int tid = threadIdx.x;
    const float* xb = x + (size_t)b * N3;
    for (int m = tid; m < NN; m += 256) {
        float qx = xb[m], qy = xb[NN + m], qz = xb[2*NN + m];
        ssq[m] = __fadd_rn(__fadd_rn(__fmul_rn(qx, qx), __fmul_rn(qy, qy)),
                           __fmul_rn(qz, qz));
    }
    __syncthreads();
    float px = xb[n], py = xb[NN + n], pz = xb[2*NN + n];
    float sqn = ssq[n];
    for (int m = tid; m < NN; m += 256) {
        float qx = xb[m], qy = xb[NN + m], qz = xb[2*NN + m];
        float dot = __fmaf_rn(pz, qz, __fmaf_rn(py, qy, __fmul_rn(px, qx)));
        sd[m] = __fsub_rn(__fadd_rn(sqn, ssq[m]), __fmul_rn(2.0f, dot));
    }
    __syncthreads();
    for (int k = 0; k < KNNK; k++) {
        float bv = INFINITY; int bi = 0x7fffffff;
        for (int m = tid; m < NN; m += 256) {
            float v = sd[m];
            if (v < bv || (v == bv && m < bi)) { bv = v; bi = m; }
        }
        for (int off = 16; off > 0; off >>= 1) {
            float ov = __shfl_down_sync(0xffffffffu, bv, off);
            int   oi = __shfl_down_sync(0xffffffffu, bi, off);
            if (ov < bv || (ov == bv && oi < bi)) { bv = ov; bi = oi; }
        }
        if ((tid & 31) == 0) { rv[tid >> 5] = bv; ri[tid >> 5] = bi; }
        __syncthreads();
        if (tid == 0) {
            float fv = rv[0]; int fi = ri[0];
            for (int w = 1; w < 8; w++)
                if (rv[w] < fv || (rv[w] == fv && ri[w] < fi)) { fv = rv[w]; fi = ri[w]; }
            g_idx[bn * KNNK + k] = fi;
            sd[fi] = INFINITY;
        }
        __syncthreads();
    }
}

// ---- pack layer weights: Wall = [W1; W2-W1; Wd@W1; Wd@(W2-W1)] ----
__global__ void wpack_k(const float* __restrict__ W, const float* __restrict__ Wd,
                        int Cin, int Cout) {
    int o = blockIdx.x;
    int c = threadIdx.x;
    if (c >= Cin) return;
    float w1 = W[o*2*Cin + c], w2 = W[o*2*Cin + Cin + c];
    g_Wall[(size_t)o * Cin + c] = w1;
    g_Wall[(size_t)(Cout + o) * Cin + c] = w2 - w1;
    float s1 = 0.f, s2 = 0.f;
    for (int m = 0; m < Cout; m++) {
        float wd = Wd[o*Cout + m];
        s1 += wd * W[m*2*Cin + c];
        s2 += wd * W[m*2*Cin + Cin + c];
    }
    g_Wall[(size_t)(2*Cout + o) * Cin + c] = s1;
    g_Wall[(size_t)(3*Cout + o) * Cin + c] = s2 - s1;
}

// ---- smem-tiled GEMM: 128 cols x 128 outs per block, K-chunks of 32 ----
__global__ __launch_bounds__(256, 2)
void gemmT_k(const float* __restrict__ Wext, int wsel,
             const float* __restrict__ xin, int finoff,
             int Cin, size_t bstride, int OutTot) {
    __shared__ float fs[32][128];
    __shared__ float ws[128][32];
    const float* Wall = wsel ? g_Wall : Wext;
    int cid0 = blockIdx.x * 128;
    int o0 = blockIdx.y * 128;
    int b = cid0 / N3;
    int dn0 = cid0 - b * N3;
    const float* fin = (xin ? xin : (g_cat + finoff)) + (size_t)b * bstride + dn0;
    int tid = threadIdx.x;
    int colg = tid & 15;   // 16 groups x 8 cols
    int rowg = tid >> 4;   // 16 groups x 8 rows
    unsigned long long acc2[8][4];
#pragma unroll
    for (int i = 0; i < 8; i++)
#pragma unroll
        for (int jp = 0; jp < 4; jp++) acc2[i][jp] = 0ULL;

    for (int kc = 0; kc < Cin; kc += 32) {
        int kmax = min(32, Cin - kc);
        __syncthreads();
        for (int idx = tid; idx < kmax * 32; idx += 256) {
            int r = idx >> 5, cq = idx & 31;
            *(float4*)&fs[r][cq*4] =
                *(const float4*)&fin[(size_t)(kc + r) * N3 + cq*4];
        }
        for (int idx = tid; idx < 128 * kmax; idx += 256) {
            int r = idx / kmax, k = idx - r * kmax;
            ws[r][k] = Wall[(size_t)(o0 + r) * Cin + kc + k];
        }
        __syncthreads();
        if (kmax == 32) {
#pragma unroll 4
            for (int k = 0; k < 32; k++) {
                ulonglong2 fa = *(const ulonglong2*)&fs[k][colg*8];
                ulonglong2 fb = *(const ulonglong2*)&fs[k][colg*8 + 4];
                unsigned long long fp0 = fa.x, fp1 = fa.y, fp2 = fb.x, fp3 = fb.y;
#pragma unroll
                for (int i = 0; i < 8; i++) {
                    float w = ws[rowg*8 + i][k];
                    unsigned long long wp = packf2(w, w);
                    fma2(acc2[i][0], wp, fp0);
                    fma2(acc2[i][1], wp, fp1);
                    fma2(acc2[i][2], wp, fp2);
                    fma2(acc2[i][3], wp, fp3);
                }
            }
        } else {
            for (int k = 0; k < kmax; k++) {
                ulonglong2 fa = *(const ulonglong2*)&fs[k][colg*8];
                ulonglong2 fb = *(const ulonglong2*)&fs[k][colg*8 + 4];
                unsigned long long fp0 = fa.x, fp1 = fa.y, fp2 = fb.x, fp3 = fb.y;
#pragma unroll
                for (int i = 0; i < 8; i++) {
                    float w = ws[rowg*8 + i][k];
                    unsigned long long wp = packf2(w, w);
                    fma2(acc2[i][0], wp, fp0);
                    fma2(acc2[i][1], wp, fp1);
                    fma2(acc2[i][2], wp, fp2);
                    fma2(acc2[i][3], wp, fp3);
                }
            }
        }
    }
    // store: cid = cid0 + colg*8 + j, o = o0 + rowg*8 + i
#pragma unroll
    for (int jp = 0; jp < 4; jp++) {
        float2 v[8];
#pragma unroll
        for (int i = 0; i < 8; i++) v[i] = unpackf2(acc2[i][jp]);
        int cidA = cid0 + colg*8 + 2*jp;
        float* opA = g_Out + (size_t)cidA * OutTot + o0 + rowg*8;
        float* opB = opA + OutTot;
        float4 a0 = make_float4(v[0].x, v[1].x, v[2].x, v[3].x);
        float4 a1 = make_float4(v[4].x, v[5].x, v[6].x, v[7].x);
        float4 b0 = make_float4(v[0].y, v[1].y, v[2].y, v[3].y);
        float4 b1 = make_float4(v[4].y, v[5].y, v[6].y, v[7].y);
        *(float4*)opA = a0; *(float4*)(opA + 4) = a1;
        *(float4*)opB = b0; *(float4*)(opB + 4) = b1;
    }
}

// ---- edge: gather + vec_act + mean over K ----
__global__ void edge_k(int Cout, int OutTot, int coff, int P) {
    int tid = threadIdx.x;
    int p = tid / Cout;
    int c = tid - p * Cout;
    int bn = blockIdx.x * P + p;
    int b = bn >> 10, n = bn & (NN - 1);
    const int* ip = g_idx + bn * KNNK;
    size_t sN = (size_t)NN * OutTot;
    size_t pn = (size_t)(b * N3 + n) * OutTot;
    float bm0 = g_Out[pn + Cout + c],   bm1 = g_Out[pn + sN + Cout + c],   bm2 = g_Out[pn + 2*sN + Cout + c];
    float bd0 = g_Out[pn + 3*Cout + c], bd1 = g_Out[pn + sN + 3*Cout + c], bd2 = g_Out[pn + 2*sN + 3*Cout + c];
    float a0 = 0.f, a1 = 0.f, a2 = 0.f;
#pragma unroll 2
    for (int k = 0; k < KNNK; k++) {
        int j = ip[k];
        size_t pj = (size_t)(b * N3 + j) * OutTot;
        float y0 = g_Out[pj + c]        + bm0;
        float y1 = g_Out[pj + sN + c]   + bm1;
        float y2 = g_Out[pj + 2*sN + c] + bm2;
        float d0 = g_Out[pj + 2*Cout + c]        + bd0;
        float d1 = g_Out[pj + sN + 2*Cout + c]   + bd1;
        float d2 = g_Out[pj + 2*sN + 2*Cout + c] + bd2;
        float dm = fmaxf(sqrtf(d0*d0 + d1*d1 + d2*d2), EPSF);
        float k0 = d0/dm, k1 = d1/dm, k2 = d2/dm;
        float dot = y0*k0 + y1*k1 + y2*k2;
        float coef = (dot < 0.f) ? (-0.8f * dot) : 0.f;
        a0 += y0 + coef*k0; a1 += y1 + coef*k1; a2 += y2 + coef*k2;
    }
    const float s = 1.0f / 16.0f;
    size_t ob = ((size_t)(b * CATC + coff + c) * 3) * NN + n;
    g_cat[ob] = a0 * s; g_cat[ob + NN] = a1 * s; g_cat[ob + 2*NN] = a2 * s;
}

// ---- g_Dc[cid] = ccD . g_Out[cid,:] (OutTot=128) ----
__global__ void dc_k(const float* __restrict__ ccD) {
    int cid = blockIdx.x * 256 + threadIdx.x;
    const float* u = g_Out + (size_t)cid * 128;
    float s = 0.f;
    for (int o = 0; o < 128; o++) s += ccD[o] * u[o];
    g_Dc[cid] = s;
}

// ---- cc vec_act with shared 1-channel direction ----
__global__ void ccact_k() {
    int bn = blockIdx.x;
    int b = bn >> 10, n = bn & (NN - 1);
    int c = threadIdx.x;
    int bn0 = b * N3 + n;
    float d0 = g_Dc[bn0], d1 = g_Dc[bn0 + NN], d2 = g_Dc[bn0 + 2*NN];
    float dm = fmaxf(sqrtf(d0*d0 + d1*d1 + d2*d2), EPSF);
    float k0 = d0/dm, k1 = d1/dm, k2 = d2/dm;
    size_t sN = (size_t)NN * 128;
    size_t p = (size_t)bn0 * 128 + c;
    float u0 = g_Out[p], u1 = g_Out[p + sN], u2 = g_Out[p + 2*sN];
    float dot = u0*k0 + u1*k1 + u2*k2;
    float coef = (dot < 0.f) ? (-0.8f * dot) : 0.f;
    size_t ob = ((size_t)(b * 128 + c) * 3) * NN + n;
    g_ycc[ob] = u0 + coef*k0; g_ycc[ob + NN] = u1 + coef*k1; g_ycc[ob + 2*NN] = u2 + coef*k2;
}

// ---- mean over N ----
__global__ void reduce_k() {
    __shared__ float s[256];
    const float* p = g_ycc + (size_t)blockIdx.x * NN;
    int t = threadIdx.x;
    s[t] = p[t] + p[t + 256] + p[t + 512] + p[t + 768];
    __syncthreads();
    for (int off = 128; off > 0; off >>= 1) {
        if (t < off) s[t] += s[t + off];
        __syncthreads();
    }
    if (t == 0) g_y[blockIdx.x] = s[0] * (1.0f / NN);
}

// ---- head helpers: 384 threads, (c, d) parallel ----
__device__ void gemm3p(float (*dst)[3], const float* __restrict__ W,
                       const float (*src)[3], int Cout, int Cin, int c, int d) {
    if (c < Cout) {
        float s = 0.f;
        for (int m = 0; m < Cin; m++) s += W[c*Cin + m] * src[m][d];
        dst[c][d] = s;
    }
    __syncthreads();
}
__device__ void act3p(float (*dst)[3], const float (*x)[3],
                      const float* __restrict__ Wd, int C, int c, int d,
                      float (*tmp)[3]) {
    if (c < C) {
        float s = 0.f;
        for (int m = 0; m < C; m++) s += Wd[c*C + m] * x[m][d];
        tmp[c][d] = s;
    }
    __syncthreads();
    if (c < C) {
        float d0 = tmp[c][0], d1 = tmp[c][1], d2 = tmp[c][2];
        float dm = fmaxf(sqrtf(d0*d0 + d1*d1 + d2*d2), EPSF);
        float k0 = d0/dm, k1 = d1/dm, k2 = d2/dm;
        float dot = x[c][0]*k0 + x[c][1]*k1 + x[c][2]*k2;
        float coef = (dot < 0.f) ? (-0.8f * dot) : 0.f;
        float kk = (d == 0) ? k0 : ((d == 1) ? k1 : k2);
        dst[c][d] = x[c][d] + coef*kk;
    }
    __syncthreads();
}

__global__ void head_k(const float* __restrict__ fcO,
                       const float* __restrict__ rbDin, const float* __restrict__ rbW0,
                       const float* __restrict__ rbDh,  const float* __restrict__ rbW1,
                       const float* __restrict__ rbWs,
                       const float* __restrict__ m0W, const float* __restrict__ m0D,
                       const float* __restrict__ m1W, const float* __restrict__ m1D,
                       const float* __restrict__ l0W, const float* __restrict__ l0D,
                       const float* __restrict__ l1W, const float* __restrict__ l1D,
                       const float* __restrict__ fimW, const float* __restrict__ filW,
                       float* __restrict__ out) {
    int b = blockIdx.x;
    int tid = threadIdx.x;
    int d = tid >> 7;         // 0..2
    int c = tid & 127;
    __shared__ float sy[128][3], syn[128][3], t0[128][3], t1[128][3], t2[128][3], tdir[128][3];
    __shared__ float snorm[128];
    __shared__ float sr[384];
    __shared__ float sR[9];
    __shared__ float sS[1];

    sy[c][d] = g_y[(b*128 + c)*3 + d];
    __syncthreads();
    if (d == 0) {
        float y0 = sy[c][0], y1 = sy[c][1], y2 = sy[c][2];
        snorm[c] = sqrtf(y0*y0 + y1*y1 + y2*y2);
    }
    __syncthreads();

    // scale = mean(nc + EPS) * 640
    if (d == 0) sr[c] = snorm[c] + EPSF;
    __syncthreads();
    for (int off = 64; off > 0; off >>= 1) {
        if (d == 0 && c < off) sr[c] += sr[c + off];
        __syncthreads();
    }
    if (tid == 0) out[1060 + b] = sr[0] * (1.0f / 128.0f) * 640.0f;
    __syncthreads();

    // S = sum nc^2 ; cevn
    if (d == 0) sr[c] = snorm[c] * snorm[c];
    __syncthreads();
    for (int off = 64; off > 0; off >>= 1) {
        if (d == 0 && c < off) sr[c] += sr[c + off];
        __syncthreads();
    }
    if (tid == 0) sS[0] = fmaxf(sqrtf(sr[0]), EPSF);
    __syncthreads();
    {
        float nn = snorm[c] / sS[0];
        float inv = fmaxf(snorm[c], EPSF);
        syn[c][d] = sy[c][d] / inv * nn;
    }
    __syncthreads();

    // R[d][o] = sum_c fcO[o][c]*syn[c][d]
    for (int o = 0; o < 3; o++) {
        sr[tid] = fcO[o*128 + c] * syn[c][d];
        __syncthreads();
        for (int off = 64; off > 0; off >>= 1) {
            if (c < off) sr[d*128 + c] += sr[d*128 + c + off];
            __syncthreads();
        }
        if (c == 0) sR[d*3 + o] = sr[d*128];
        __syncthreads();
    }

    // polar (det-scaled Newton); so3_out = transpose(Q)
    if (tid == 0) {
        float X[9], Cf[9];
        float fn = 0.f;
        for (int i = 0; i < 9; i++) { X[i] = sR[i]; fn += X[i]*X[i]; }
        fn = sqrtf(fn); if (fn < 1e-20f) fn = 1e-20f;
        for (int i = 0; i < 9; i++) X[i] /= fn;
        for (int it = 0; it < 25; it++) {
            Cf[0] =  (X[4]*X[8] - X[5]*X[7]);
            Cf[1] = -(X[3]*X[8] - X[5]*X[6]);
            Cf[2] =  (X[3]*X[7] - X[4]*X[6]);
            Cf[3] = -(X[1]*X[8] - X[2]*X[7]);
            Cf[4] =  (X[0]*X[8] - X[2]*X[6]);
            Cf[5] = -(X[0]*X[7] - X[1]*X[6]);
            Cf[6] =  (X[1]*X[5] - X[2]*X[4]);
            Cf[7] = -(X[0]*X[5] - X[2]*X[3]);
            Cf[8] =  (X[0]*X[4] - X[1]*X[3]);
            float det = X[0]*Cf[0] + X[1]*Cf[1] + X[2]*Cf[2];
            float ad = fabsf(det);
            if (ad < 1e-30f) break;
            float z = 1.0f / cbrtf(ad);
            float invd = 1.0f / det;
            for (int i = 0; i < 9; i++)
                X[i] = 0.5f * (z * X[i] + (Cf[i] * invd) / z);
        }
        for (int i = 0; i < 3; i++)
            for (int j = 0; j < 3; j++)
                out[1024 + b*9 + i*3 + j] = X[j*3 + i];
    }

    // residual block: center
    act3p(t0, sy, rbDin, 128, c, d, tdir);
    gemm3p(t1, rbW0, t0, 64, 128, c, d);
    act3p(t2, t1, rbDh, 64, c, d, tdir);
    if (tid < 3) {
        float dx = 0.f;
        for (int m = 0; m < 64; m++) dx += rbW1[m] * t2[m][tid];
        float wsv = 0.f;
        for (int m = 0; m < 128; m++) wsv += rbWs[m] * sy[m][tid];
        out[1064 + b*3 + tid] = (wsv + dx) * 640.0f;
    }
    __syncthreads();

    // mean branch
    gemm3p(t0, m0W, syn, 128, 128, c, d);
    act3p(t1, t0, m0D, 128, c, d, tdir);
    gemm3p(t0, m1W, t1, 128, 128, c, d);
    act3p(t2, t0, m1D, 128, c, d, tdir);
    gemm3p(t0, fimW, t2, 128, 128, c, d);
    if (d == 0)
        out[b*128 + c] = t2[c][0]*t0[c][0] + t2[c][1]*t0[c][1] + t2[c][2]*t0[c][2];
    __syncthreads();

    // logvar branch
    gemm3p(t0, l0W, syn, 128, 128, c, d);
    act3p(t1, t0, l0D, 128, c, d, tdir);
    gemm3p(t0, l1W, t1, 128, 128, c, d);
    act3p(t2, t0, l1D, 128, c, d, tdir);
    gemm3p(t0, filW, t2, 128, 128, c, d);
    if (d == 0)
        out[512 + b*128 + c] = t2[c][0]*t0[c][0] + t2[c][1]*t0[c][1] + t2[c][2]*t0[c][2];
}

// ---- host-side layer driver ----
static void run_layer(const float* W, const float* Wd, int Cin, int Cout,
                      const float* xin, int finoff, size_t bstride, int coff) {
    int OutTot = 4 * Cout;
    wpack_k<<<Cout, Cin>>>(W, Wd, Cin, Cout);
    dim3 g(96, OutTot / 128);
    gemmT_k<<<g, 256>>>(nullptr, 1, xin, finoff, Cin, bstride, OutTot);
    int P = 128 / Cout;
    edge_k<<<BB * NN / P, 128>>>(Cout, OutTot, coff, P);
}

extern "C" void kernel_launch(void* const* d_in, const int* in_sizes, int n_in,
                              void* d_out, int out_size) {
    const float* x    = (const float*)d_in[0];
    const float* c1W  = (const float*)d_in[2];
    const float* c1D  = (const float*)d_in[3];
    const float* c2W  = (const float*)d_in[4];
    const float* c2D  = (const float*)d_in[5];
    const float* c3W  = (const float*)d_in[6];
    const float* c3D  = (const float*)d_in[7];
    const float* c4W  = (const float*)d_in[8];
    const float* c4D  = (const float*)d_in[9];
    const float* ccW  = (const float*)d_in[10];
    const float* ccD  = (const float*)d_in[11];
    const float* fcO  = (const float*)d_in[12];
    const float* m0W  = (const float*)d_in[13];
    const float* m0D  = (const float*)d_in[14];
    const float* m1W  = (const float*)d_in[15];
    const float* m1D  = (const float*)d_in[16];
    const float* l0W  = (const float*)d_in[17];
    const float* l0D  = (const float*)d_in[18];
    const float* l1W  = (const float*)d_in[19];
    const float* l1D  = (const float*)d_in[20];
    const float* fimW = (const float*)d_in[21];
    const float* filW = (const float*)d_in[22];
    const float* rbDin= (const float*)d_in[23];
    const float* rbW0 = (const float*)d_in[24];
    const float* rbDh = (const float*)d_in[25];
    const float* rbW1 = (const float*)d_in[26];
    const float* rbWs = (const float*)d_in[27];
    float* out = (float*)d_out;

    knn_k<<<BB * NN, 256>>>(x);

    size_t catbs = (size_t)CATC * N3;
    run_layer(c1W, c1D, 1,   32,  x,       0,        (size_t)N3, 0);
    run_layer(c2W, c2D, 32,  64,  nullptr, 0,        catbs,      32);
    run_layer(c3W, c3D, 64,  128, nullptr, 32 * N3,  catbs,      96);
    run_layer(c4W, c4D, 128, 128, nullptr, 96 * N3,  catbs,      224);

    // cc layer: U = ccW @ cat  (OutTot=128, weights direct)
    {
        dim3 g(96, 1);
        gemmT_k<<<g, 256>>>(ccW, 0, nullptr, 0, CATC, catbs, 128);
    }
    dc_k<<<48, 256>>>(ccD);
    ccact_k<<<BB * NN, 128>>>();
    reduce_k<<<BB * 128 * 3, 256>>>();

    head_k<<<BB, 384>>>(fcO, rbDin, rbW0, rbDh, rbW1, rbWs,
                        m0W, m0D, m1W, m1D, l0W, l0D, l1W, l1D,
                        fimW, filW, out);
}